// round 5
// baseline (speedup 1.0000x reference)
#include <cuda_runtime.h>
#include <cuda_fp16.h>
#include <cstdint>
#include <cstddef>

#define B_ 2
#define H_ 16
#define L_ 2048
#define S_ 2048
#define D_ 64
#define TR 16
#define SK 128
#define NTHREADS 512

// fp16 copy of values (scratch; __device__ global per allocation rules)
__device__ __half g_v16[(size_t)B_ * S_ * H_ * D_];

__global__ void convert_v_kernel(const float* __restrict__ v) {
    int i = blockIdx.x * blockDim.x + threadIdx.x;   // over float4s
    const float4* v4 = (const float4*)v;
    float4 f = v4[i];
    __half2* dst = (__half2*)g_v16;
    dst[2 * i]     = __floats2half2_rn(f.x, f.y);
    dst[2 * i + 1] = __floats2half2_rn(f.z, f.w);
}

// ---- smem layout (bytes) ----
#define A_STRIDE 136   // halves: 272B rows -> conflict-free ldmatrix
#define V_STRIDE 72    // halves: 144B rows -> conflict-free ldmatrix.trans
#define OFF_E   0
#define OFF_A   (TR * S_ * 2)                     // 65536
#define OFF_V   (OFF_A + 2 * TR * A_STRIDE * 2)   // 74240 (16B aligned)
#define VBUF_B  (SK * V_STRIDE * 2)               // 18432 per V buffer
#define OFF_DEN (OFF_V + 2 * VBUF_B)              // 111104
#define SMEM_BYTES (OFF_DEN + 64)                 // 111168 -> 2 CTAs/SM

// phase-1 score staging ring (3 x 8KB), reusing A region + V buffer 1
// band layout: [16 rows][128 cols] fp32, row stride 512B
#define STAGE_B 8192

__device__ __forceinline__ uint32_t h2u(__half2 h) { return *reinterpret_cast<uint32_t*>(&h); }
__device__ __forceinline__ __half2 u2h(uint32_t u) { return *reinterpret_cast<__half2*>(&u); }

__global__ void __launch_bounds__(NTHREADS, 2)
attn_kernel(const float* __restrict__ scores, float* __restrict__ out) {
    extern __shared__ char smem[];
    __half* Es = (__half*)(smem + OFF_E);
    float*  den = (float*)(smem + OFF_DEN);
    float*  sumbuf = (float*)(smem + OFF_V);   // reused after last MMA

    const int l0 = blockIdx.x * TR;
    const int bh = blockIdx.y;          // b*H + h
    const int b  = bh >> 4;
    const int h  = bh & 15;

    const int tid  = threadIdx.x;
    const int wid  = tid >> 5;
    const int lane = tid & 31;

    const uint32_t As_u = (uint32_t)__cvta_generic_to_shared(smem + OFF_A);
    const uint32_t Vh_u = (uint32_t)__cvta_generic_to_shared(smem + OFF_V);
    const __half* vbase = g_v16 + ((size_t)b * S_ * H_ + h) * D_;
    const int nc = (l0 + TR + SK - 1) / SK;

    // ---- prefetch V chunk 0 (1 group) ----
    {
        #pragma unroll
        for (int i = 0; i < 2; ++i) {
            int idx = tid + i * NTHREADS;
            int r = idx >> 3, q = idx & 7;
            const void* src = (const void*)(vbase + (size_t)r * (H_ * D_) + q * 8);
            uint32_t dst = Vh_u + r * (V_STRIDE * 2) + q * 16;
            asm volatile("cp.async.cg.shared.global [%0], [%1], 16;\n" :: "r"(dst), "l"(src) : "memory");
        }
        asm volatile("cp.async.commit_group;\n" ::: "memory");
    }

    // ---- Phase 1: cp.async-staged score pass; e=exp(x), z=sum; fp16 e -> Es (causal cols only) ----
    float invz;
    {
        // per-thread fixed slots: warp w stages/reads only row w; thread stages its own 16B
        const char* gsrc = (const char*)(scores + ((size_t)bh * L_ + l0 + wid) * S_) + lane * 16;
        const uint32_t st_base[3] = {
            As_u + (uint32_t)(wid * 512 + lane * 16),
            Vh_u + (uint32_t)(VBUF_B + wid * 512 + lane * 16),
            Vh_u + (uint32_t)(VBUF_B + STAGE_B + wid * 512 + lane * 16)
        };
        const char* st_rd[3] = {
            smem + OFF_A + wid * 512 + lane * 16,
            smem + OFF_V + VBUF_B + wid * 512 + lane * 16,
            smem + OFF_V + VBUF_B + STAGE_B + wid * 512 + lane * 16
        };
        // prefetch bands 0,1
        asm volatile("cp.async.cg.shared.global [%0], [%1], 16;\ncp.async.commit_group;\n"
                     :: "r"(st_base[0]), "l"(gsrc) : "memory");
        asm volatile("cp.async.cg.shared.global [%0], [%1], 16;\ncp.async.commit_group;\n"
                     :: "r"(st_base[1]), "l"(gsrc + 512) : "memory");

        const int last_band = (l0 + TR - 1) >> 7;   // bands above this are never read back
        uint2* erow = (uint2*)(Es + wid * S_);
        float z = 0.f;
        #pragma unroll
        for (int i = 0; i < 16; ++i) {
            if (i < 15) { asm volatile("cp.async.wait_group 1;\n" ::: "memory"); }
            else        { asm volatile("cp.async.wait_group 0;\n" ::: "memory"); }
            float4 f = *(const float4*)st_rd[i % 3];
            float e0 = __expf(f.x), e1 = __expf(f.y), e2 = __expf(f.z), e3 = __expf(f.w);
            z += (e0 + e1) + (e2 + e3);
            if (i <= last_band) {
                uint2 u;
                u.x = h2u(__floats2half2_rn(e0, e1));
                u.y = h2u(__floats2half2_rn(e2, e3));
                erow[i * 32 + lane] = u;
            }
            if (i + 2 < 16) {
                asm volatile("cp.async.cg.shared.global [%0], [%1], 16;\ncp.async.commit_group;\n"
                             :: "r"(st_base[(i + 2) % 3]), "l"(gsrc + (i + 2) * 512) : "memory");
            }
        }
        #pragma unroll
        for (int o = 16; o; o >>= 1) z += __shfl_xor_sync(0xffffffffu, z, o);
        invz = 1.f / z;
    }
    __syncthreads();   // stage regions (A buf / V buf1) now reusable by all warps

    // ---- Phase 2: chunk loop. A = poly_exp(e*invz) masked; C += A @ V ----
    const int lrow = l0 + wid;
    const int kh = wid >> 2;             // k-quarter 0..3
    const int nq = wid & 3;              // n-quarter 0..3
    const int n0 = nq * 16;
    const int ar = lane & 15;
    const int ac = (lane >> 4) * 8;
    const int brow = lane & 15;
    const int bcol = n0 + (lane >> 4) * 8;
    float denom = 0.f;
    float c0 = 0.f, c1 = 0.f, c2 = 0.f, c3 = 0.f;
    float c4 = 0.f, c5 = 0.f, c6 = 0.f, c7 = 0.f;

    for (int c = 0; c < nc; ++c) {
        const int s0 = c * SK;
        const uint32_t abuf = As_u + (c & 1) * (TR * A_STRIDE * 2);
        const uint32_t vbuf = Vh_u + (c & 1) * VBUF_B;

        // A chunk: warp w computes its own row (4 halves/lane), cubic exp(w)=1+w+w^2/2+w^3/6
        {
            uint2 ee = *((const uint2*)(Es + wid * S_ + s0) + lane);
            float2 f01 = __half22float2(u2h(ee.x));
            float2 f23 = __half22float2(u2h(ee.y));
            float w0 = f01.x * invz, w1 = f01.y * invz, w2 = f23.x * invz, w3 = f23.y * invz;
            float a0 = fmaf(w0, fmaf(w0, fmaf(w0, 0.16666667f, 0.5f), 1.f), 1.f);
            float a1 = fmaf(w1, fmaf(w1, fmaf(w1, 0.16666667f, 0.5f), 1.f), 1.f);
            float a2 = fmaf(w2, fmaf(w2, fmaf(w2, 0.16666667f, 0.5f), 1.f), 1.f);
            float a3 = fmaf(w3, fmaf(w3, fmaf(w3, 0.16666667f, 0.5f), 1.f), 1.f);
            if (s0 + SK - 1 > lrow) {   // diagonal chunk for this warp: mask
                int sb = s0 + lane * 4;
                a0 = (sb + 0 <= lrow) ? a0 : 0.f;
                a1 = (sb + 1 <= lrow) ? a1 : 0.f;
                a2 = (sb + 2 <= lrow) ? a2 : 0.f;
                a3 = (sb + 3 <= lrow) ? a3 : 0.f;
            }
            __half2 o01 = __floats2half2_rn(a0, a1);
            __half2 o23 = __floats2half2_rn(a2, a3);
            float2 r01 = __half22float2(o01);
            float2 r23 = __half22float2(o23);
            denom += (r01.x + r01.y) + (r23.x + r23.y);
            uint2 u; u.x = h2u(o01); u.y = h2u(o23);
            *((uint2*)(smem + OFF_A) + ((c & 1) * TR * A_STRIDE + wid * A_STRIDE) / 4 + lane) = u;
        }

        asm volatile("cp.async.wait_group 0;\n" ::: "memory");   // V chunk c resident
        __syncthreads();                                         // A visible; prev MMA done

        if (c + 1 < nc) {
            const int s1 = s0 + SK;
            const uint32_t dstb = Vh_u + ((c + 1) & 1) * VBUF_B;
            #pragma unroll
            for (int i = 0; i < 2; ++i) {
                int idx = tid + i * NTHREADS;
                int r = idx >> 3, q = idx & 7;
                const void* src = (const void*)(vbase + (size_t)(s1 + r) * (H_ * D_) + q * 8);
                uint32_t dst = dstb + r * (V_STRIDE * 2) + q * 16;
                asm volatile("cp.async.cg.shared.global [%0], [%1], 16;\n" :: "r"(dst), "l"(src) : "memory");
            }
        }
        asm volatile("cp.async.commit_group;\n" ::: "memory");

        // MMA: warp handles k-quarter kh (2 k-steps) x n-pair (n0, n0+8)
        #pragma unroll
        for (int t = 0; t < 2; ++t) {
            int kk = kh * 2 + t;
            uint32_t a0r, a1r, a2r, a3r, b0, b1, b2, b3;
            uint32_t aaddr = abuf + (uint32_t)((ar * A_STRIDE + kk * 16 + ac) * 2);
            asm volatile("ldmatrix.sync.aligned.m8n8.x4.shared.b16 {%0,%1,%2,%3}, [%4];\n"
                         : "=r"(a0r), "=r"(a1r), "=r"(a2r), "=r"(a3r) : "r"(aaddr));
            uint32_t baddr = vbuf + (uint32_t)(((kk * 16 + brow) * V_STRIDE + bcol) * 2);
            asm volatile("ldmatrix.sync.aligned.m8n8.x4.trans.shared.b16 {%0,%1,%2,%3}, [%4];\n"
                         : "=r"(b0), "=r"(b1), "=r"(b2), "=r"(b3) : "r"(baddr));
            asm volatile("mma.sync.aligned.m16n8k16.row.col.f32.f16.f16.f32 "
                         "{%0,%1,%2,%3},{%4,%5,%6,%7},{%8,%9},{%0,%1,%2,%3};\n"
                         : "+f"(c0), "+f"(c1), "+f"(c2), "+f"(c3)
                         : "r"(a0r), "r"(a1r), "r"(a2r), "r"(a3r), "r"(b0), "r"(b1));
            asm volatile("mma.sync.aligned.m16n8k16.row.col.f32.f16.f16.f32 "
                         "{%0,%1,%2,%3},{%4,%5,%6,%7},{%8,%9},{%0,%1,%2,%3};\n"
                         : "+f"(c4), "+f"(c5), "+f"(c6), "+f"(c7)
                         : "r"(a0r), "r"(a1r), "r"(a2r), "r"(a3r), "r"(b2), "r"(b3));
        }
    }

    // ---- Epilogue ----
    #pragma unroll
    for (int o = 16; o; o >>= 1) denom += __shfl_xor_sync(0xffffffffu, denom, o);
    if (lane == 0) den[wid] = denom;
    __syncthreads();   // den visible; all MMA done -> V region reusable

    if (kh > 0) {      // warps 4..15 dump fragments
        float* p = sumbuf + (wid - 4) * 256 + lane * 8;
        p[0] = c0; p[1] = c1; p[2] = c2; p[3] = c3;
        p[4] = c4; p[5] = c5; p[6] = c6; p[7] = c7;
    }
    __syncthreads();

    if (kh == 0) {     // warps 0..3 reduce the 4 k-parts and store
        #pragma unroll
        for (int p = 0; p < 3; ++p) {
            const float* q = sumbuf + (p * 4 + nq) * 256 + lane * 8;
            c0 += q[0]; c1 += q[1]; c2 += q[2]; c3 += q[3];
            c4 += q[4]; c5 += q[5]; c6 += q[6]; c7 += q[7];
        }
        int r1  = lane >> 2;
        int col = n0 + (lane & 3) * 2;
        float i1 = 1.f / den[r1];
        float i2 = 1.f / den[r1 + 8];
        size_t o1 = ((size_t)(b * L_ + l0 + r1) * H_ + h) * D_ + col;
        size_t o2 = ((size_t)(b * L_ + l0 + r1 + 8) * H_ + h) * D_ + col;
        out[o1]         = c0 * i1;
        out[o1 + 1]     = c1 * i1;
        out[o2]         = c2 * i2;
        out[o2 + 1]     = c3 * i2;
        out[o1 + 8]     = c4 * i1;
        out[o1 + 9]     = c5 * i1;
        out[o2 + 8]     = c6 * i2;
        out[o2 + 9]     = c7 * i2;
    }
}

extern "C" void kernel_launch(void* const* d_in, const int* in_sizes, int n_in,
                              void* d_out, int out_size) {
    // inputs: 0=queries (unused), 1=keys (unused), 2=values [B,S,H,D] f32, 3=scores [B,H,L,S] f32
    const float* values = (const float*)d_in[2];
    const float* scores = (const float*)d_in[3];
    float* out = (float*)d_out;

    convert_v_kernel<<<(B_ * S_ * H_ * D_ / 4) / NTHREADS, NTHREADS>>>(values);

    cudaFuncSetAttribute(attn_kernel, cudaFuncAttributeMaxDynamicSharedMemorySize, SMEM_BYTES);
    dim3 grid(L_ / TR, B_ * H_);
    attn_kernel<<<grid, NTHREADS, SMEM_BYTES>>>(scores, out);
}

// round 6
// speedup vs baseline: 1.0030x; 1.0030x over previous
#include <cuda_runtime.h>
#include <cuda_fp16.h>
#include <cstdint>
#include <cstddef>

#define B_ 2
#define H_ 16
#define L_ 2048
#define S_ 2048
#define D_ 64
#define TR 16
#define SK 128
#define NTHREADS 512

// fp16 copy of values (scratch; __device__ global per allocation rules)
__device__ __half g_v16[(size_t)B_ * S_ * H_ * D_];

__global__ void convert_v_kernel(const float* __restrict__ v) {
    int i = blockIdx.x * blockDim.x + threadIdx.x;   // over float4s
    const float4* v4 = (const float4*)v;
    float4 f = v4[i];
    __half2* dst = (__half2*)g_v16;
    dst[2 * i]     = __floats2half2_rn(f.x, f.y);
    dst[2 * i + 1] = __floats2half2_rn(f.z, f.w);
}

// ---- smem layout (bytes) ----
#define A_STRIDE 136   // halves: 272B rows -> conflict-free ldmatrix
#define V_STRIDE 72    // halves: 144B rows -> conflict-free ldmatrix.trans
#define OFF_E   0
#define OFF_A   (TR * S_ * 2)                     // 65536
#define OFF_V   (OFF_A + 2 * TR * A_STRIDE * 2)   // 74240 (16B aligned)
#define VBUF_B  (SK * V_STRIDE * 2)               // 18432 per V buffer
#define OFF_DEN (OFF_V + 2 * VBUF_B)              // 111104
#define SMEM_BYTES (OFF_DEN + 64)                 // 111168 -> 2 CTAs/SM

// phase-1 score staging ring (3 x 8KB), reusing A region + V buffer 1
// band layout: [16 rows][128 cols] fp32, row stride 512B
#define STAGE_B 8192

__device__ __forceinline__ uint32_t h2u(__half2 h) { return *reinterpret_cast<uint32_t*>(&h); }
__device__ __forceinline__ __half2 u2h(uint32_t u) { return *reinterpret_cast<__half2*>(&u); }

__global__ void __launch_bounds__(NTHREADS, 2)
attn_kernel(const float* __restrict__ scores, float* __restrict__ out) {
    extern __shared__ char smem[];
    __half* Es = (__half*)(smem + OFF_E);
    float*  den = (float*)(smem + OFF_DEN);
    float*  sumbuf = (float*)(smem + OFF_V);   // reused after last MMA

    const int l0 = blockIdx.x * TR;
    const int bh = blockIdx.y;          // b*H + h
    const int b  = bh >> 4;
    const int h  = bh & 15;

    const int tid  = threadIdx.x;
    const int wid  = tid >> 5;
    const int lane = tid & 31;

    const uint32_t As_u = (uint32_t)__cvta_generic_to_shared(smem + OFF_A);
    const uint32_t Vh_u = (uint32_t)__cvta_generic_to_shared(smem + OFF_V);
    const __half* vbase = g_v16 + ((size_t)b * S_ * H_ + h) * D_;
    const int nc = (l0 + TR + SK - 1) / SK;

    // ---- prefetch V chunk 0 (1 group) ----
    {
        #pragma unroll
        for (int i = 0; i < 2; ++i) {
            int idx = tid + i * NTHREADS;
            int r = idx >> 3, q = idx & 7;
            const void* src = (const void*)(vbase + (size_t)r * (H_ * D_) + q * 8);
            uint32_t dst = Vh_u + r * (V_STRIDE * 2) + q * 16;
            asm volatile("cp.async.cg.shared.global [%0], [%1], 16;\n" :: "r"(dst), "l"(src) : "memory");
        }
        asm volatile("cp.async.commit_group;\n" ::: "memory");
    }

    // ---- Phase 1: cp.async-staged score pass; e=exp(x), z=sum; fp16 e -> Es (causal cols only) ----
    float invz;
    {
        // per-thread fixed slots: warp w stages/reads only row w; thread stages its own 16B
        const char* gsrc = (const char*)(scores + ((size_t)bh * L_ + l0 + wid) * S_) + lane * 16;
        const uint32_t st_base[3] = {
            As_u + (uint32_t)(wid * 512 + lane * 16),
            Vh_u + (uint32_t)(VBUF_B + wid * 512 + lane * 16),
            Vh_u + (uint32_t)(VBUF_B + STAGE_B + wid * 512 + lane * 16)
        };
        const char* st_rd[3] = {
            smem + OFF_A + wid * 512 + lane * 16,
            smem + OFF_V + VBUF_B + wid * 512 + lane * 16,
            smem + OFF_V + VBUF_B + STAGE_B + wid * 512 + lane * 16
        };
        // prefetch bands 0,1
        asm volatile("cp.async.cg.shared.global [%0], [%1], 16;\ncp.async.commit_group;\n"
                     :: "r"(st_base[0]), "l"(gsrc) : "memory");
        asm volatile("cp.async.cg.shared.global [%0], [%1], 16;\ncp.async.commit_group;\n"
                     :: "r"(st_base[1]), "l"(gsrc + 512) : "memory");

        const int last_band = (l0 + TR - 1) >> 7;   // bands above this are never read back
        uint2* erow = (uint2*)(Es + wid * S_);
        float z = 0.f;
        #pragma unroll
        for (int i = 0; i < 16; ++i) {
            if (i < 15) { asm volatile("cp.async.wait_group 1;\n" ::: "memory"); }
            else        { asm volatile("cp.async.wait_group 0;\n" ::: "memory"); }
            float4 f = *(const float4*)st_rd[i % 3];
            float e0 = __expf(f.x), e1 = __expf(f.y), e2 = __expf(f.z), e3 = __expf(f.w);
            z += (e0 + e1) + (e2 + e3);
            if (i <= last_band) {
                uint2 u;
                u.x = h2u(__floats2half2_rn(e0, e1));
                u.y = h2u(__floats2half2_rn(e2, e3));
                erow[i * 32 + lane] = u;
            }
            if (i + 2 < 16) {
                asm volatile("cp.async.cg.shared.global [%0], [%1], 16;\ncp.async.commit_group;\n"
                             :: "r"(st_base[(i + 2) % 3]), "l"(gsrc + (i + 2) * 512) : "memory");
            }
        }
        #pragma unroll
        for (int o = 16; o; o >>= 1) z += __shfl_xor_sync(0xffffffffu, z, o);
        invz = 1.f / z;
    }
    __syncthreads();   // stage regions (A buf / V buf1) now reusable by all warps

    // ---- Phase 2: chunk loop. A = poly_exp(e*invz) masked; C += A @ V ----
    const int lrow = l0 + wid;
    const int kh = wid >> 2;             // k-quarter 0..3
    const int nq = wid & 3;              // n-quarter 0..3
    const int n0 = nq * 16;
    const int ar = lane & 15;
    const int ac = (lane >> 4) * 8;
    const int brow = lane & 15;
    const int bcol = n0 + (lane >> 4) * 8;
    float denom = 0.f;
    float c0 = 0.f, c1 = 0.f, c2 = 0.f, c3 = 0.f;
    float c4 = 0.f, c5 = 0.f, c6 = 0.f, c7 = 0.f;

    for (int c = 0; c < nc; ++c) {
        const int s0 = c * SK;
        const uint32_t abuf = As_u + (c & 1) * (TR * A_STRIDE * 2);
        const uint32_t vbuf = Vh_u + (c & 1) * VBUF_B;

        // A chunk: warp w computes its own row (4 halves/lane), cubic exp(w)=1+w+w^2/2+w^3/6
        {
            uint2 ee = *((const uint2*)(Es + wid * S_ + s0) + lane);
            float2 f01 = __half22float2(u2h(ee.x));
            float2 f23 = __half22float2(u2h(ee.y));
            float w0 = f01.x * invz, w1 = f01.y * invz, w2 = f23.x * invz, w3 = f23.y * invz;
            float a0 = fmaf(w0, fmaf(w0, fmaf(w0, 0.16666667f, 0.5f), 1.f), 1.f);
            float a1 = fmaf(w1, fmaf(w1, fmaf(w1, 0.16666667f, 0.5f), 1.f), 1.f);
            float a2 = fmaf(w2, fmaf(w2, fmaf(w2, 0.16666667f, 0.5f), 1.f), 1.f);
            float a3 = fmaf(w3, fmaf(w3, fmaf(w3, 0.16666667f, 0.5f), 1.f), 1.f);
            if (s0 + SK - 1 > lrow) {   // diagonal chunk for this warp: mask
                int sb = s0 + lane * 4;
                a0 = (sb + 0 <= lrow) ? a0 : 0.f;
                a1 = (sb + 1 <= lrow) ? a1 : 0.f;
                a2 = (sb + 2 <= lrow) ? a2 : 0.f;
                a3 = (sb + 3 <= lrow) ? a3 : 0.f;
            }
            __half2 o01 = __floats2half2_rn(a0, a1);
            __half2 o23 = __floats2half2_rn(a2, a3);
            float2 r01 = __half22float2(o01);
            float2 r23 = __half22float2(o23);
            denom += (r01.x + r01.y) + (r23.x + r23.y);
            uint2 u; u.x = h2u(o01); u.y = h2u(o23);
            *((uint2*)(smem + OFF_A) + ((c & 1) * TR * A_STRIDE + wid * A_STRIDE) / 4 + lane) = u;
        }

        asm volatile("cp.async.wait_group 0;\n" ::: "memory");   // V chunk c resident
        __syncthreads();                                         // A visible; prev MMA done

        if (c + 1 < nc) {
            const int s1 = s0 + SK;
            const uint32_t dstb = Vh_u + ((c + 1) & 1) * VBUF_B;
            #pragma unroll
            for (int i = 0; i < 2; ++i) {
                int idx = tid + i * NTHREADS;
                int r = idx >> 3, q = idx & 7;
                const void* src = (const void*)(vbase + (size_t)(s1 + r) * (H_ * D_) + q * 8);
                uint32_t dst = dstb + r * (V_STRIDE * 2) + q * 16;
                asm volatile("cp.async.cg.shared.global [%0], [%1], 16;\n" :: "r"(dst), "l"(src) : "memory");
            }
        }
        asm volatile("cp.async.commit_group;\n" ::: "memory");

        // MMA: warp handles k-quarter kh (2 k-steps) x n-pair (n0, n0+8)
        #pragma unroll
        for (int t = 0; t < 2; ++t) {
            int kk = kh * 2 + t;
            uint32_t a0r, a1r, a2r, a3r, b0, b1, b2, b3;
            uint32_t aaddr = abuf + (uint32_t)((ar * A_STRIDE + kk * 16 + ac) * 2);
            asm volatile("ldmatrix.sync.aligned.m8n8.x4.shared.b16 {%0,%1,%2,%3}, [%4];\n"
                         : "=r"(a0r), "=r"(a1r), "=r"(a2r), "=r"(a3r) : "r"(aaddr));
            uint32_t baddr = vbuf + (uint32_t)(((kk * 16 + brow) * V_STRIDE + bcol) * 2);
            asm volatile("ldmatrix.sync.aligned.m8n8.x4.trans.shared.b16 {%0,%1,%2,%3}, [%4];\n"
                         : "=r"(b0), "=r"(b1), "=r"(b2), "=r"(b3) : "r"(baddr));
            asm volatile("mma.sync.aligned.m16n8k16.row.col.f32.f16.f16.f32 "
                         "{%0,%1,%2,%3},{%4,%5,%6,%7},{%8,%9},{%0,%1,%2,%3};\n"
                         : "+f"(c0), "+f"(c1), "+f"(c2), "+f"(c3)
                         : "r"(a0r), "r"(a1r), "r"(a2r), "r"(a3r), "r"(b0), "r"(b1));
            asm volatile("mma.sync.aligned.m16n8k16.row.col.f32.f16.f16.f32 "
                         "{%0,%1,%2,%3},{%4,%5,%6,%7},{%8,%9},{%0,%1,%2,%3};\n"
                         : "+f"(c4), "+f"(c5), "+f"(c6), "+f"(c7)
                         : "r"(a0r), "r"(a1r), "r"(a2r), "r"(a3r), "r"(b2), "r"(b3));
        }
    }

    // ---- Epilogue ----
    #pragma unroll
    for (int o = 16; o; o >>= 1) denom += __shfl_xor_sync(0xffffffffu, denom, o);
    if (lane == 0) den[wid] = denom;
    __syncthreads();   // den visible; all MMA done -> V region reusable

    if (kh > 0) {      // warps 4..15 dump fragments
        float* p = sumbuf + (wid - 4) * 256 + lane * 8;
        p[0] = c0; p[1] = c1; p[2] = c2; p[3] = c3;
        p[4] = c4; p[5] = c5; p[6] = c6; p[7] = c7;
    }
    __syncthreads();

    if (kh == 0) {     // warps 0..3 reduce the 4 k-parts and store
        #pragma unroll
        for (int p = 0; p < 3; ++p) {
            const float* q = sumbuf + (p * 4 + nq) * 256 + lane * 8;
            c0 += q[0]; c1 += q[1]; c2 += q[2]; c3 += q[3];
            c4 += q[4]; c5 += q[5]; c6 += q[6]; c7 += q[7];
        }
        int r1  = lane >> 2;
        int col = n0 + (lane & 3) * 2;
        float i1 = 1.f / den[r1];
        float i2 = 1.f / den[r1 + 8];
        size_t o1 = ((size_t)(b * L_ + l0 + r1) * H_ + h) * D_ + col;
        size_t o2 = ((size_t)(b * L_ + l0 + r1 + 8) * H_ + h) * D_ + col;
        out[o1]         = c0 * i1;
        out[o1 + 1]     = c1 * i1;
        out[o2]         = c2 * i2;
        out[o2 + 1]     = c3 * i2;
        out[o1 + 8]     = c4 * i1;
        out[o1 + 9]     = c5 * i1;
        out[o2 + 8]     = c6 * i2;
        out[o2 + 9]     = c7 * i2;
    }
}

extern "C" void kernel_launch(void* const* d_in, const int* in_sizes, int n_in,
                              void* d_out, int out_size) {
    // inputs: 0=queries (unused), 1=keys (unused), 2=values [B,S,H,D] f32, 3=scores [B,H,L,S] f32
    const float* values = (const float*)d_in[2];
    const float* scores = (const float*)d_in[3];
    float* out = (float*)d_out;

    convert_v_kernel<<<(B_ * S_ * H_ * D_ / 4) / NTHREADS, NTHREADS>>>(values);

    cudaFuncSetAttribute(attn_kernel, cudaFuncAttributeMaxDynamicSharedMemorySize, SMEM_BYTES);
    dim3 grid(L_ / TR, B_ * H_);
    attn_kernel<<<grid, NTHREADS, SMEM_BYTES>>>(scores, out);
}